// round 9
// baseline (speedup 1.0000x reference)
#include <cuda_runtime.h>
#include <cuda_bf16.h>
#include <math.h>
#include <float.h>
#include <stdint.h>

#define BD 256      // batch
#define DD 4096     // dim

// Scratch (allocation-free: device globals)
// M = W + W^T decomposed exactly: M = S1*2^-8 + S2*2^-15 + S3*2^-22 + eps(|eps|<=2^-23)
__device__ signed char g_S1[(size_t)DD * DD];      // 16MB
__device__ signed char g_S2[(size_t)DD * DD];      // 16MB
__device__ signed char g_S3[(size_t)DD * DD];      // 16MB
__device__ signed char g_X8[(size_t)BD * DD];      // x as s8 (exact: binary)
__device__ float       g_grad[(size_t)BD * DD];    // grad = 0.5*M*x + b

// ===========================================================================
// helpers
// ===========================================================================
__device__ __forceinline__ uint32_t smem_u32(const void* p) {
    uint32_t a;
    asm("{ .reg .u64 t; cvta.to.shared.u64 t, %1; cvt.u32.u64 %0, t; }" : "=r"(a) : "l"(p));
    return a;
}
__device__ __forceinline__ void cp16(uint32_t s, const void* g) {
    asm volatile("cp.async.cg.shared.global [%0], [%1], 16;\n" :: "r"(s), "l"(g));
}
#define CP_COMMIT() asm volatile("cp.async.commit_group;\n" ::: "memory")
#define CP_WAIT1()  asm volatile("cp.async.wait_group 1;\n" ::: "memory")

__device__ __forceinline__ void ldmx4(uint32_t* r, uint32_t a) {
    asm volatile("ldmatrix.sync.aligned.m8n8.x4.shared.b16 {%0,%1,%2,%3}, [%4];\n"
                 : "=r"(r[0]), "=r"(r[1]), "=r"(r[2]), "=r"(r[3]) : "r"(a));
}
__device__ __forceinline__ void mma_s8(int* d, const uint32_t* a, uint32_t b0, uint32_t b1) {
    asm volatile(
        "mma.sync.aligned.m16n8k32.row.col.s32.s8.s8.s32 "
        "{%0,%1,%2,%3}, {%4,%5,%6,%7}, {%8,%9}, {%0,%1,%2,%3};\n"
        : "+r"(d[0]), "+r"(d[1]), "+r"(d[2]), "+r"(d[3])
        : "r"(a[0]), "r"(a[1]), "r"(a[2]), "r"(a[3]), "r"(b0), "r"(b1));
}
__device__ __forceinline__ uint32_t swz(uint32_t off) {   // SW128: bits[6:4] ^= bits[9:7]
    return off ^ ((off >> 3) & 0x70);
}

// ---------------------------------------------------------------------------
// Kernel 1: M = W + W^T -> 3 int8 fixed-point slabs. 64x64 tile pairs,
// W read once; 8B packed stores per slab.
// ---------------------------------------------------------------------------
__device__ __forceinline__ void quant3(float a, signed char* o1, signed char* o2, signed char* o3) {
    float s1 = rintf(a * 256.f);              // |s1| <= ~80 << 127
    float r1 = a - s1 * 0x1p-8f;              // |r1| <= 2^-9
    float s2 = rintf(r1 * 32768.f);           // |s2| <= 64
    float r2 = r1 - s2 * 0x1p-15f;            // |r2| <= 2^-16
    float s3 = rintf(r2 * 4194304.f);         // |s3| <= 64
    *o1 = (signed char)(int)s1;
    *o2 = (signed char)(int)s2;
    *o3 = (signed char)(int)s3;
}

__global__ __launch_bounds__(256) void k_buildM(const float* __restrict__ W) {
    int bx = blockIdx.x, by = blockIdx.y;
    if (by > bx) return;
    __shared__ float t1[64][65];
    __shared__ float t2[64][65];
    int tid = threadIdx.x;
    int r1 = by * 64, c1 = bx * 64;
    bool diag = (bx == by);

    #pragma unroll
    for (int i = 0; i < 4; i++) {
        int chunk = tid + i * 256;
        int row = chunk >> 4;
        int c4  = (chunk & 15) * 4;
        float4 v1 = *(const float4*)&W[(size_t)(r1 + row) * DD + c1 + c4];
        t1[row][c4] = v1.x; t1[row][c4+1] = v1.y; t1[row][c4+2] = v1.z; t1[row][c4+3] = v1.w;
        if (!diag) {
            float4 v2 = *(const float4*)&W[(size_t)(c1 + row) * DD + r1 + c4];
            t2[row][c4] = v2.x; t2[row][c4+1] = v2.y; t2[row][c4+2] = v2.z; t2[row][c4+3] = v2.w;
        } else {
            t2[row][c4] = v1.x; t2[row][c4+1] = v1.y; t2[row][c4+2] = v1.z; t2[row][c4+3] = v1.w;
        }
    }
    __syncthreads();

    #pragma unroll
    for (int i = 0; i < 2; i++) {
        int u   = tid + i * 256;      // 0..511
        int row = u >> 3;             // 64 rows
        int cg  = (u & 7) * 8;        // 8-col group
        {
            __align__(8) signed char o1[8], o2[8], o3[8];
            #pragma unroll
            for (int e = 0; e < 8; e++) {
                float a = t1[row][cg + e] + t2[cg + e][row];
                quant3(a, &o1[e], &o2[e], &o3[e]);
            }
            size_t off = (size_t)(r1 + row) * DD + c1 + cg;
            *(uint2*)&g_S1[off] = *(uint2*)o1;
            *(uint2*)&g_S2[off] = *(uint2*)o2;
            *(uint2*)&g_S3[off] = *(uint2*)o3;
        }
        if (!diag) {
            __align__(8) signed char o1[8], o2[8], o3[8];
            #pragma unroll
            for (int e = 0; e < 8; e++) {
                float a = t2[row][cg + e] + t1[cg + e][row];
                quant3(a, &o1[e], &o2[e], &o3[e]);
            }
            size_t off = (size_t)(c1 + row) * DD + r1 + cg;
            *(uint2*)&g_S1[off] = *(uint2*)o1;
            *(uint2*)&g_S2[off] = *(uint2*)o2;
            *(uint2*)&g_S3[off] = *(uint2*)o3;
        }
    }
}

// ---------------------------------------------------------------------------
// Kernel 2: x -> s8 (exact: x is 0/1). 16 elems/thread.
// ---------------------------------------------------------------------------
__global__ void k_convX(const float* __restrict__ x) {
    int i = (blockIdx.x * 256 + threadIdx.x) * 16;
    __align__(16) signed char v[16];
    #pragma unroll
    for (int g = 0; g < 4; g++) {
        float4 f = *(const float4*)&x[i + g * 4];
        v[g*4+0] = (signed char)(int)f.x;
        v[g*4+1] = (signed char)(int)f.y;
        v[g*4+2] = (signed char)(int)f.z;
        v[g*4+3] = (signed char)(int)f.w;
    }
    *(uint4*)&g_X8[i] = *(uint4*)v;
}

// ---------------------------------------------------------------------------
// Kernel 3: int8 GEMM  grad = 0.5*(A1*2^-8 + A2*2^-15 + A3*2^-22) + bias
// BM=BN=64, BK=128 (128B int8 rows), 128 threads, 3-stage cp.async (dist 2).
// B slabs use symmetry: B[n][k] = S[n0+n][k0+k] -> plain row loads, no trans.
// mma.m16n8k32.s8: 4096 MAC/inst, exact s32 accumulation.
// Grid (64, 4) = 256 CTAs, occ 2 (96KB smem).
// ---------------------------------------------------------------------------
#define TM 64
#define TN 64
#define BKI 128
#define NITI (DD / BKI)            // 32
#define TI 8192                    // 64 rows x 128B
#define STG_B (4 * TI)             // A + 3 slabs = 32KB
#define GSMEM (3 * STG_B + 1024)   // 97KB -> occ 2

extern __shared__ char g_dynsm[];

__global__ __launch_bounds__(128) void k_gemm(const float* __restrict__ bias) {
    int tid  = threadIdx.x;
    int lane = tid & 31, w = tid >> 5;
    int m0 = blockIdx.y * TM;
    int n0 = blockIdx.x * TN;
    int wm = (w >> 1) * 32;
    int wn = (w & 1) * 32;

    uint32_t base = (smem_u32(g_dynsm) + 1023u) & ~1023u;

    int acc[3][2][4][4];
    #pragma unroll
    for (int s = 0; s < 3; s++)
        #pragma unroll
        for (int a = 0; a < 2; a++)
            #pragma unroll
            for (int b = 0; b < 4; b++)
                #pragma unroll
                for (int c = 0; c < 4; c++) acc[s][a][b][c] = 0;

    const signed char* gA  = g_X8 + (size_t)m0 * DD;
    const signed char* gB1 = g_S1 + (size_t)n0 * DD;
    const signed char* gB2 = g_S2 + (size_t)n0 * DD;
    const signed char* gB3 = g_S3 + (size_t)n0 * DD;

    auto load_stage = [&](int s, int it) {
        int k0 = it * BKI;
        uint32_t sb = base + s * STG_B;
        #pragma unroll
        for (int i = 0; i < 4; i++) {
            int id  = tid + i * 128;      // 0..511
            int row = id >> 3;            // 64 rows
            int cb  = (id & 7) * 16;      // byte col within 128B row
            uint32_t d = swz((uint32_t)(row * 128 + cb));
            cp16(sb + d,          gA  + (size_t)row * DD + k0 + cb);
            cp16(sb + TI + d,     gB1 + (size_t)row * DD + k0 + cb);
            cp16(sb + 2*TI + d,   gB2 + (size_t)row * DD + k0 + cb);
            cp16(sb + 3*TI + d,   gB3 + (size_t)row * DD + k0 + cb);
        }
    };

    load_stage(0, 0); CP_COMMIT();
    load_stage(1, 1); CP_COMMIT();

    // A-fragment addressing (same pattern as verified bf16 path, byte-scaled)
    int lm   = lane & 15;                 // row within 16
    int lh16 = (lane >> 4) * 16;          // +16B for upper half-warp
    // B-fragment addressing (no trans; tiles: (n0-7,kb),(n0-7,kb+16),(n8-15,kb),(n8-15,kb+16))
    int brow  = ((lane >> 4) & 1) * 8 + (lane & 7);
    int bbyte = ((lane >> 3) & 1) * 16;

    for (int it = 0; it < NITI; it++) {
        int s = it % 3;
        CP_WAIT1();
        __syncthreads();
        if (it + 2 < NITI) load_stage((it + 2) % 3, it + 2);
        CP_COMMIT();

        uint32_t sbA = base + s * STG_B;

        #pragma unroll
        for (int ks = 0; ks < 4; ks++) {
            int kb = ks * 32;
            uint32_t af[2][4];
            #pragma unroll
            for (int mt = 0; mt < 2; mt++)
                ldmx4(af[mt], sbA + swz((uint32_t)((wm + mt * 16 + lm) * 128 + kb + lh16)));
            #pragma unroll
            for (int sl = 0; sl < 3; sl++) {
                uint32_t sbB = sbA + (sl + 1) * TI;
                #pragma unroll
                for (int nh = 0; nh < 2; nh++) {
                    uint32_t bfr[4];
                    ldmx4(bfr, sbB + swz((uint32_t)((wn + nh * 16 + brow) * 128 + kb + bbyte)));
                    #pragma unroll
                    for (int mt = 0; mt < 2; mt++) {
                        mma_s8(acc[sl][mt][nh * 2 + 0], af[mt], bfr[0], bfr[1]);
                        mma_s8(acc[sl][mt][nh * 2 + 1], af[mt], bfr[2], bfr[3]);
                    }
                }
            }
        }
    }

    // epilogue: grad = acc1*2^-9 + acc2*2^-16 + acc3*2^-23 + bias  (0.5 folded in)
    int r = lane >> 2, c2 = (lane & 3) * 2;
    #pragma unroll
    for (int mt = 0; mt < 2; mt++)
        #pragma unroll
        for (int nt = 0; nt < 4; nt++) {
            int grow = m0 + wm + mt * 16 + r;
            int gcol = n0 + wn + nt * 8 + c2;
            float b0v = bias[gcol], b1v = bias[gcol + 1];
            #pragma unroll
            for (int e = 0; e < 4; e++) {
                float g = __int2float_rn(acc[0][mt][nt][e]) * 0x1p-9f
                        + __int2float_rn(acc[1][mt][nt][e]) * 0x1p-16f
                        + __int2float_rn(acc[2][mt][nt][e]) * 0x1p-23f
                        + ((e & 1) ? b1v : b0v);
                int rr = grow + (e >> 1) * 8;
                int cc = gcol + (e & 1);
                g_grad[(size_t)rr * DD + cc] = g;
            }
        }
}

// ---------------------------------------------------------------------------
// Kernel 4: per-row sampler (unchanged, verified ~18us).
// ---------------------------------------------------------------------------
#define ST 256
#define NW (ST / 32)

__global__ __launch_bounds__(ST) void k_sample(
    const float* __restrict__ x, const float* __restrict__ W,
    const int* __restrict__ radius_raw, const float* __restrict__ gum,
    const float* __restrict__ u, float* __restrict__ out)
{
    int row = blockIdx.x;
    int tid = threadIdx.x;
    int lane = tid & 31, wid = tid >> 5;

    __shared__ float s_wval[NW];
    __shared__ int   s_widx[NW];
    __shared__ float s_red[NW];
    __shared__ int   s_win;
    __shared__ int   s_idx[16];

    const float* xr  = x      + (size_t)row * DD;
    const float* gr  = g_grad + (size_t)row * DD;
    const float* gur = gum    + (size_t)row * DD;

    float4 vx[4], vg[4], vu[4];
    #pragma unroll
    for (int g = 0; g < 4; g++) vx[g] = *(const float4*)&xr[g * 1024 + tid * 4];
    #pragma unroll
    for (int g = 0; g < 4; g++) vg[g] = *(const float4*)&gr[g * 1024 + tid * 4];
    #pragma unroll
    for (int g = 0; g < 4; g++) vu[g] = *(const float4*)&gur[g * 1024 + tid * 4];

    float xv[16], scx[16], key[16];
    #pragma unroll
    for (int g = 0; g < 4; g++) {
        float fx[4] = {vx[g].x, vx[g].y, vx[g].z, vx[g].w};
        float fg[4] = {vg[g].x, vg[g].y, vg[g].z, vg[g].w};
        float fu[4] = {vu[g].x, vu[g].y, vu[g].z, vu[g].w};
        #pragma unroll
        for (int e = 0; e < 4; e++) {
            int k = g * 4 + e;
            xv[k]  = fx[e];
            scx[k] = (0.5f - fx[e]) * fg[e];
            float uu = fminf(fmaxf(fu[e], 1e-10f), 1.0f - 1e-10f);
            key[k] = scx[k] - __logf(-__logf(uu));
        }
    }

    // ---- lse_x ----
    float m = -FLT_MAX;
    #pragma unroll
    for (int k = 0; k < 16; k++) m = fmaxf(m, scx[k]);
    #pragma unroll
    for (int o = 16; o > 0; o >>= 1) m = fmaxf(m, __shfl_xor_sync(0xffffffffu, m, o));
    if (lane == 0) s_red[wid] = m;
    __syncthreads();
    float mx = s_red[0];
    #pragma unroll
    for (int ww = 1; ww < NW; ww++) mx = fmaxf(mx, s_red[ww]);
    __syncthreads();
    float s = 0.f;
    #pragma unroll
    for (int k = 0; k < 16; k++) s += __expf(scx[k] - mx);
    #pragma unroll
    for (int o = 16; o > 0; o >>= 1) s += __shfl_xor_sync(0xffffffffu, s, o);
    if (lane == 0) s_red[wid] = s;
    __syncthreads();
    float ss = 0.f;
    #pragma unroll
    for (int ww = 0; ww < NW; ww++) ss += s_red[ww];
    float lse_x = mx + logf(ss);

    // ---- initial per-warp candidate ----
    {
        float bv = -FLT_MAX; int bk = 0;
        #pragma unroll
        for (int k = 0; k < 16; k++)
            if (key[k] > bv) { bv = key[k]; bk = k; }
        int bj = (bk >> 2) * 1024 + tid * 4 + (bk & 3);
        #pragma unroll
        for (int o = 16; o > 0; o >>= 1) {
            float v2 = __shfl_down_sync(0xffffffffu, bv, o);
            int   i2 = __shfl_down_sync(0xffffffffu, bj, o);
            if (v2 > bv || (v2 == bv && i2 < bj)) { bv = v2; bj = i2; }
        }
        if (lane == 0) { s_wval[wid] = bv; s_widx[wid] = bj; }
    }
    __syncthreads();

    // ---- top-radius: 2 barriers/iter, winner-warp-only rescan ----
    int radius = radius_raw[row] + 1;
    for (int t = 0; t < radius; t++) {
        if (tid == 0) {
            float wv = s_wval[0]; int wj = s_widx[0]; int wwin = 0;
            #pragma unroll
            for (int ww = 1; ww < NW; ww++) {
                float v2 = s_wval[ww]; int i2 = s_widx[ww];
                if (v2 > wv || (v2 == wv && i2 < wj)) { wv = v2; wj = i2; wwin = ww; }
            }
            s_idx[t] = wj; s_win = wwin;
        }
        __syncthreads();
        if (wid == s_win && t + 1 < radius) {
            int j = s_idx[t];
            if (((j & 1023) >> 2) == tid) key[(j >> 10) * 4 + (j & 3)] = -FLT_MAX;
            float bv = -FLT_MAX; int bk = 0;
            #pragma unroll
            for (int k = 0; k < 16; k++)
                if (key[k] > bv) { bv = key[k]; bk = k; }
            int bj = (bk >> 2) * 1024 + tid * 4 + (bk & 3);
            #pragma unroll
            for (int o = 16; o > 0; o >>= 1) {
                float v2 = __shfl_down_sync(0xffffffffu, bv, o);
                int   i2 = __shfl_down_sync(0xffffffffu, bj, o);
                if (v2 > bv || (v2 == bv && i2 < bj)) { bv = v2; bj = i2; }
            }
            if (lane == 0) { s_wval[wid] = bv; s_widx[wid] = bj; }
        }
        __syncthreads();
    }

    unsigned mask = 0;
    for (int t = 0; t < radius; t++) {
        int j = s_idx[t];
        if (((j & 1023) >> 2) == tid) mask |= 1u << ((j >> 10) * 4 + (j & 3));
    }

    // ---- quad = 0.5 * d^T W d over flipped positions ----
    float q = 0.f;
    int rr = radius * radius;
    for (int p = tid; p < rr; p += ST) {
        int a = p / radius, bb = p - a * radius;
        int ia = s_idx[a], ib = s_idx[bb];
        float da = 1.f - 2.f * xr[ia];
        float db = 1.f - 2.f * xr[ib];
        q += da * db * W[(size_t)ia * DD + ib];
    }
    #pragma unroll
    for (int o = 16; o > 0; o >>= 1) q += __shfl_xor_sync(0xffffffffu, q, o);
    __syncthreads();
    if (lane == 0) s_red[wid] = q;
    __syncthreads();
    float quad = 0.f;
    #pragma unroll
    for (int ww = 0; ww < NW; ww++) quad += s_red[ww];
    quad *= 0.5f;
    __syncthreads();

    // ---- lse_y ----
    float m2 = -FLT_MAX;
    #pragma unroll
    for (int k = 0; k < 16; k++) {
        float v = (mask >> k) & 1 ? -scx[k] : scx[k];
        m2 = fmaxf(m2, v);
    }
    #pragma unroll
    for (int o = 16; o > 0; o >>= 1) m2 = fmaxf(m2, __shfl_xor_sync(0xffffffffu, m2, o));
    if (lane == 0) s_red[wid] = m2;
    __syncthreads();
    float mx2 = s_red[0];
    #pragma unroll
    for (int ww = 1; ww < NW; ww++) mx2 = fmaxf(mx2, s_red[ww]);
    __syncthreads();
    float s2 = 0.f;
    #pragma unroll
    for (int k = 0; k < 16; k++) {
        float v = (mask >> k) & 1 ? -scx[k] : scx[k];
        s2 += __expf(v - mx2);
    }
    #pragma unroll
    for (int o = 16; o > 0; o >>= 1) s2 += __shfl_xor_sync(0xffffffffu, s2, o);
    if (lane == 0) s_red[wid] = s2;
    __syncthreads();
    float ss2 = 0.f;
    #pragma unroll
    for (int ww = 0; ww < NW; ww++) ss2 += s_red[ww];
    float lse_y = mx2 + logf(ss2);

    // ---- accept + write ----
    float la = fminf(quad + lse_x - lse_y, 0.f);
    int accept = (__expf(la) > u[row]) ? 1 : 0;

    float* outr = out + (size_t)row * DD;
    #pragma unroll
    for (int g = 0; g < 4; g++) {
        int base = g * 1024 + tid * 4;
        float4 o4;
        float* po = (float*)&o4;
        #pragma unroll
        for (int e = 0; e < 4; e++) {
            int k = g * 4 + e;
            float yv = ((mask >> k) & 1) ? (1.f - xv[k]) : xv[k];
            po[e] = accept ? yv : xv[k];
        }
        *(float4*)&outr[base] = o4;
    }
}

// ---------------------------------------------------------------------------
extern "C" void kernel_launch(void* const* d_in, const int* in_sizes, int n_in,
                              void* d_out, int out_size) {
    const float* x          = (const float*)d_in[0];
    const float* W          = (const float*)d_in[1];
    const float* bias       = (const float*)d_in[2];
    const int*   radius_raw = (const int*)d_in[3];
    const float* gum        = (const float*)d_in[4];
    const float* u          = (const float*)d_in[5];
    float* out = (float*)d_out;

    cudaFuncSetAttribute(k_gemm, cudaFuncAttributeMaxDynamicSharedMemorySize, GSMEM);

    k_buildM<<<dim3(DD / 64, DD / 64), 256>>>(W);
    k_convX<<<(BD * DD) / 4096, 256>>>(x);
    k_gemm<<<dim3(DD / TN, BD / TM), 128, GSMEM>>>(bias);
    k_sample<<<BD, ST>>>(x, W, radius_raw, gum, u, out);
}

// round 10
// speedup vs baseline: 2.3409x; 2.3409x over previous
#include <cuda_runtime.h>
#include <cuda_bf16.h>
#include <math.h>
#include <float.h>
#include <stdint.h>

#define BD 256      // batch
#define DD 4096     // dim

// Scratch (allocation-free: device globals)
__device__ __nv_bfloat16 g_Mhi[(size_t)DD * DD];   // bf16 hi of W + W^T (symmetric)
__device__ __nv_bfloat16 g_Mlo[(size_t)DD * DD];   // bf16 residual (symmetric)
__device__ __nv_bfloat16 g_Xbf[(size_t)BD * DD];   // x in bf16 (exact: binary)
__device__ float         g_grad[(size_t)BD * DD];  // grad = 0.5(W+W^T)x + b
// sampler split scratch
__device__ float g_pm[BD * 4];                     // per-chunk max
__device__ float g_ps[BD * 4];                     // per-chunk sumexp
__device__ float g_cv[BD * 64];                    // candidate values (4 chunks x 16)
__device__ int   g_ci[BD * 64];                    // candidate indices
__device__ int   g_fidx[BD * 16];                  // flip indices
__device__ int   g_cnt[BD];                        // accept ? radius : 0

// ===========================================================================
// helpers
// ===========================================================================
__device__ __forceinline__ uint32_t smem_u32(const void* p) {
    uint32_t a;
    asm("{ .reg .u64 t; cvta.to.shared.u64 t, %1; cvt.u32.u64 %0, t; }" : "=r"(a) : "l"(p));
    return a;
}
__device__ __forceinline__ void cp16(uint32_t s, const void* g) {
    asm volatile("cp.async.cg.shared.global [%0], [%1], 16;\n" :: "r"(s), "l"(g));
}
#define CP_COMMIT() asm volatile("cp.async.commit_group;\n" ::: "memory")
#define CP_WAIT2()  asm volatile("cp.async.wait_group 2;\n" ::: "memory")

__device__ __forceinline__ void ldmx4(uint32_t* r, uint32_t a) {
    asm volatile("ldmatrix.sync.aligned.m8n8.x4.shared.b16 {%0,%1,%2,%3}, [%4];\n"
                 : "=r"(r[0]), "=r"(r[1]), "=r"(r[2]), "=r"(r[3]) : "r"(a));
}
__device__ __forceinline__ void ldmx4t(uint32_t* r, uint32_t a) {
    asm volatile("ldmatrix.sync.aligned.m8n8.x4.trans.shared.b16 {%0,%1,%2,%3}, [%4];\n"
                 : "=r"(r[0]), "=r"(r[1]), "=r"(r[2]), "=r"(r[3]) : "r"(a));
}
__device__ __forceinline__ void mma16816(float* d, const uint32_t* a, uint32_t b0, uint32_t b1) {
    asm volatile(
        "mma.sync.aligned.m16n8k16.row.col.f32.bf16.bf16.f32 "
        "{%0,%1,%2,%3}, {%4,%5,%6,%7}, {%8,%9}, {%0,%1,%2,%3};\n"
        : "+f"(d[0]), "+f"(d[1]), "+f"(d[2]), "+f"(d[3])
        : "r"(a[0]), "r"(a[1]), "r"(a[2]), "r"(a[3]), "r"(b0), "r"(b1));
}
__device__ __forceinline__ uint32_t swz(uint32_t off) {   // SW128
    return off ^ ((off >> 3) & 0x70);
}
// butterfly argmax over a warp: all lanes converge to (v, i) of winner
__device__ __forceinline__ void warp_argmax(float& v, int& i) {
    #pragma unroll
    for (int o = 16; o > 0; o >>= 1) {
        float v2 = __shfl_xor_sync(0xffffffffu, v, o);
        int   i2 = __shfl_xor_sync(0xffffffffu, i, o);
        if (v2 > v || (v2 == v && i2 < i)) { v = v2; i = i2; }
    }
}

// ---------------------------------------------------------------------------
// Kernel 1: M = W + W^T -> bf16 hi + bf16 lo (R7, verified)
// ---------------------------------------------------------------------------
__global__ __launch_bounds__(256) void k_buildM(const float* __restrict__ W) {
    int bx = blockIdx.x, by = blockIdx.y;
    if (by > bx) return;
    __shared__ float t1[64][65];
    __shared__ float t2[64][65];
    int tid = threadIdx.x;
    int r1 = by * 64, c1 = bx * 64;
    bool diag = (bx == by);

    #pragma unroll
    for (int i = 0; i < 4; i++) {
        int chunk = tid + i * 256;
        int row = chunk >> 4;
        int c4  = (chunk & 15) * 4;
        float4 v1 = *(const float4*)&W[(size_t)(r1 + row) * DD + c1 + c4];
        t1[row][c4] = v1.x; t1[row][c4+1] = v1.y; t1[row][c4+2] = v1.z; t1[row][c4+3] = v1.w;
        if (!diag) {
            float4 v2 = *(const float4*)&W[(size_t)(c1 + row) * DD + r1 + c4];
            t2[row][c4] = v2.x; t2[row][c4+1] = v2.y; t2[row][c4+2] = v2.z; t2[row][c4+3] = v2.w;
        } else {
            t2[row][c4] = v1.x; t2[row][c4+1] = v1.y; t2[row][c4+2] = v1.z; t2[row][c4+3] = v1.w;
        }
    }
    __syncthreads();

    #pragma unroll
    for (int i = 0; i < 2; i++) {
        int u   = tid + i * 256;
        int row = u >> 3;
        int cg  = (u & 7) * 8;
        {
            __align__(16) __nv_bfloat16 hi[8], lo[8];
            #pragma unroll
            for (int e = 0; e < 8; e++) {
                float a = t1[row][cg + e] + t2[cg + e][row];
                __nv_bfloat16 h = __float2bfloat16(a);
                hi[e] = h;
                lo[e] = __float2bfloat16(a - __bfloat162float(h));
            }
            size_t off = (size_t)(r1 + row) * DD + c1 + cg;
            *(uint4*)&g_Mhi[off] = *(uint4*)hi;
            *(uint4*)&g_Mlo[off] = *(uint4*)lo;
        }
        if (!diag) {
            __align__(16) __nv_bfloat16 hi[8], lo[8];
            #pragma unroll
            for (int e = 0; e < 8; e++) {
                float a = t2[row][cg + e] + t1[cg + e][row];
                __nv_bfloat16 h = __float2bfloat16(a);
                hi[e] = h;
                lo[e] = __float2bfloat16(a - __bfloat162float(h));
            }
            size_t off = (size_t)(c1 + row) * DD + r1 + cg;
            *(uint4*)&g_Mhi[off] = *(uint4*)hi;
            *(uint4*)&g_Mlo[off] = *(uint4*)lo;
        }
    }
}

// ---------------------------------------------------------------------------
// Kernel 2: x -> bf16
// ---------------------------------------------------------------------------
__global__ void k_convX(const float* __restrict__ x) {
    int i = (blockIdx.x * 256 + threadIdx.x) * 4;
    float4 v = *(const float4*)&x[i];
    __nv_bfloat162 p0; p0.x = __float2bfloat16(v.x); p0.y = __float2bfloat16(v.y);
    __nv_bfloat162 p1; p1.x = __float2bfloat16(v.z); p1.y = __float2bfloat16(v.w);
    *(__nv_bfloat162*)&g_Xbf[i]     = p0;
    *(__nv_bfloat162*)&g_Xbf[i + 2] = p1;
}

// ---------------------------------------------------------------------------
// Kernel 3: GEMM  grad = 0.5 * (Xbf @ Mhi + Xbf @ Mlo) + bias
// R7 skeleton; inner loop reordered: all-hi MMAs then all-lo MMAs to break
// back-to-back RAW on each accumulator.
// ---------------------------------------------------------------------------
#define TM 64
#define TN 64
#define TKK 64
#define GNIT (DD / TKK)          // 64
#define GTILE 8192               // 64 rows x 128B
#define GSTAGE_B (3 * GTILE)     // 24KB
#define GSMEM (4 * GSTAGE_B + 1024)

extern __shared__ char g_dynsm[];

__global__ __launch_bounds__(128) void k_gemm(const float* __restrict__ bias) {
    int tid  = threadIdx.x;
    int lane = tid & 31, w = tid >> 5;
    int m0 = blockIdx.y * TM;
    int n0 = blockIdx.x * TN;
    int wm = (w >> 1) * 32;
    int wn = (w & 1) * 32;

    uint32_t base = (smem_u32(g_dynsm) + 1023u) & ~1023u;

    float acc[2][4][4];
    #pragma unroll
    for (int a = 0; a < 2; a++)
        #pragma unroll
        for (int b = 0; b < 4; b++)
            #pragma unroll
            for (int c = 0; c < 4; c++) acc[a][b][c] = 0.f;

    const __nv_bfloat16* gA = g_Xbf + (size_t)m0 * DD;
    const __nv_bfloat16* gH = g_Mhi + (size_t)n0;
    const __nv_bfloat16* gL = g_Mlo + (size_t)n0;

    auto load_stage = [&](int s, int it) {
        int k0 = it * TKK;
        uint32_t sb = base + s * GSTAGE_B;
        #pragma unroll
        for (int i = 0; i < 4; i++) {
            int id  = tid + i * 128;
            int row = id >> 3;
            int ce  = (id & 7) * 8;
            uint32_t d = swz((uint32_t)(row * 128 + ce * 2));
            cp16(sb + d,              gA + (size_t)row * DD + it * TKK + ce);
            cp16(sb + GTILE + d,      gH + (size_t)(k0 + row) * DD + ce);
            cp16(sb + 2 * GTILE + d,  gL + (size_t)(k0 + row) * DD + ce);
        }
    };

    #pragma unroll
    for (int s = 0; s < 3; s++) { load_stage(s, s); CP_COMMIT(); }

    int lm = lane & 15, lh = (lane >> 4) * 8;

    for (int it = 0; it < GNIT; it++) {
        int s = it & 3;
        CP_WAIT2();
        __syncthreads();
        if (it + 3 < GNIT) load_stage((it + 3) & 3, it + 3);
        CP_COMMIT();

        uint32_t sbA = base + s * GSTAGE_B;
        uint32_t sbH = sbA + GTILE;
        uint32_t sbL = sbA + 2 * GTILE;

        #pragma unroll
        for (int ks = 0; ks < TKK; ks += 16) {
            uint32_t af[2][4], bh[2][4], bl[2][4];
            #pragma unroll
            for (int mt = 0; mt < 2; mt++) {
                uint32_t byte = (uint32_t)((wm + mt * 16 + lm) * 128 + (ks + lh) * 2);
                ldmx4(af[mt], sbA + swz(byte));
            }
            #pragma unroll
            for (int nb = 0; nb < 2; nb++) {
                uint32_t byte = (uint32_t)((ks + lm) * 128 + (wn + nb * 16 + lh) * 2);
                ldmx4t(bh[nb], sbH + swz(byte));
                ldmx4t(bl[nb], sbL + swz(byte));
            }
            // all hi-MMAs (8 independent accumulator chains) ...
            #pragma unroll
            for (int nt = 0; nt < 4; nt++) {
                int nb = nt >> 1, sel = (nt & 1) * 2;
                #pragma unroll
                for (int mt = 0; mt < 2; mt++)
                    mma16816(acc[mt][nt], af[mt], bh[nb][sel], bh[nb][sel + 1]);
            }
            // ... then all lo-MMAs (each depends on its hi 8 insts earlier)
            #pragma unroll
            for (int nt = 0; nt < 4; nt++) {
                int nb = nt >> 1, sel = (nt & 1) * 2;
                #pragma unroll
                for (int mt = 0; mt < 2; mt++)
                    mma16816(acc[mt][nt], af[mt], bl[nb][sel], bl[nb][sel + 1]);
            }
        }
    }

    int r = lane >> 2, c2 = (lane & 3) * 2;
    #pragma unroll
    for (int mt = 0; mt < 2; mt++)
        #pragma unroll
        for (int nt = 0; nt < 4; nt++) {
            int grow = m0 + wm + mt * 16 + r;
            int gcol = n0 + wn + nt * 8 + c2;
            float b0v = bias[gcol], b1v = bias[gcol + 1];
            g_grad[(size_t)grow * DD + gcol]           = 0.5f * acc[mt][nt][0] + b0v;
            g_grad[(size_t)grow * DD + gcol + 1]       = 0.5f * acc[mt][nt][1] + b1v;
            g_grad[(size_t)(grow + 8) * DD + gcol]     = 0.5f * acc[mt][nt][2] + b0v;
            g_grad[(size_t)(grow + 8) * DD + gcol + 1] = 0.5f * acc[mt][nt][3] + b1v;
        }
}

// ---------------------------------------------------------------------------
// Kernel 4a: per-(row, chunk-of-1024) partials. Grid (4, BD), 256 threads.
// Computes chunk (max, sumexp) of scx and chunk top-16 Gumbel candidates
// (shuffle-only argmax; barriers only between the two phases).
// ---------------------------------------------------------------------------
__global__ __launch_bounds__(256) void k_part(
    const float* __restrict__ x, const float* __restrict__ gum)
{
    int chunk = blockIdx.x, row = blockIdx.y;
    int tid = threadIdx.x, lane = tid & 31, wid = tid >> 5;
    int cbase = chunk * 1024;

    __shared__ float s_red[8];
    __shared__ float s_sum[8];
    __shared__ float s_cv[8][16];
    __shared__ int   s_ci[8][16];

    size_t goff = (size_t)row * DD + cbase + tid * 4;
    float4 fx = *(const float4*)&x[goff];
    float4 fg = *(const float4*)&g_grad[goff];
    float4 fu = *(const float4*)&gum[goff];

    float scx[4], key[4];
    {
        float ax[4] = {fx.x, fx.y, fx.z, fx.w};
        float ag[4] = {fg.x, fg.y, fg.z, fg.w};
        float au[4] = {fu.x, fu.y, fu.z, fu.w};
        #pragma unroll
        for (int e = 0; e < 4; e++) {
            scx[e] = (0.5f - ax[e]) * ag[e];
            float uu = fminf(fmaxf(au[e], 1e-10f), 1.0f - 1e-10f);
            key[e] = scx[e] - __logf(-__logf(uu));
        }
    }

    // chunk max
    float m = fmaxf(fmaxf(scx[0], scx[1]), fmaxf(scx[2], scx[3]));
    #pragma unroll
    for (int o = 16; o > 0; o >>= 1) m = fmaxf(m, __shfl_xor_sync(0xffffffffu, m, o));
    if (lane == 0) s_red[wid] = m;
    __syncthreads();
    float cm = s_red[0];
    #pragma unroll
    for (int ww = 1; ww < 8; ww++) cm = fmaxf(cm, s_red[ww]);
    // chunk sumexp
    float s = __expf(scx[0] - cm) + __expf(scx[1] - cm) + __expf(scx[2] - cm) + __expf(scx[3] - cm);
    #pragma unroll
    for (int o = 16; o > 0; o >>= 1) s += __shfl_xor_sync(0xffffffffu, s, o);
    __syncthreads();
    if (lane == 0) s_sum[wid] = s;

    // per-warp top-16 (shuffle only)
    #pragma unroll 1
    for (int t = 0; t < 16; t++) {
        float bv = key[0]; int be = 0;
        #pragma unroll
        for (int e = 1; e < 4; e++) if (key[e] > bv) { bv = key[e]; be = e; }
        int bj = cbase + tid * 4 + be;
        warp_argmax(bv, bj);
        if (((bj - cbase) >> 2) == tid) key[bj & 3] = -FLT_MAX;
        if (lane == 0) { s_cv[wid][t] = bv; s_ci[wid][t] = bj; }
    }
    __syncthreads();

    if (tid == 0) {
        float tot = 0.f;
        #pragma unroll
        for (int ww = 0; ww < 8; ww++) tot += s_sum[ww];
        g_pm[row * 4 + chunk] = cm;
        g_ps[row * 4 + chunk] = tot;
    }

    // warp 0 merges 128 candidates -> top-16
    if (wid == 0) {
        float v4[4]; int i4[4];
        #pragma unroll
        for (int j = 0; j < 4; j++) {
            int c = lane * 4 + j;
            v4[j] = s_cv[c >> 4][c & 15];
            i4[j] = s_ci[c >> 4][c & 15];
        }
        #pragma unroll 1
        for (int t = 0; t < 16; t++) {
            float bv = v4[0]; int bi = i4[0];
            #pragma unroll
            for (int j = 1; j < 4; j++)
                if (v4[j] > bv || (v4[j] == bv && i4[j] < bi)) { bv = v4[j]; bi = i4[j]; }
            warp_argmax(bv, bi);
            #pragma unroll
            for (int j = 0; j < 4; j++) if (i4[j] == bi) v4[j] = -FLT_MAX;
            if (lane == 0) {
                g_cv[row * 64 + chunk * 16 + t] = bv;
                g_ci[row * 64 + chunk * 16 + t] = bi;
            }
        }
    }
}

// ---------------------------------------------------------------------------
// Kernel 4b: per-row finalize. Grid BD, 128 threads.
// lse_x from partials; top-radius from 64 candidates (warp 0); quad gather;
// lse_y via exact flip-correction; accept; flip list to global.
// ---------------------------------------------------------------------------
__global__ __launch_bounds__(128) void k_fin(
    const float* __restrict__ x, const float* __restrict__ W,
    const int* __restrict__ radius_raw, const float* __restrict__ u)
{
    int row = blockIdx.x;
    int tid = threadIdx.x, lane = tid & 31, wid = tid >> 5;

    __shared__ int   s_idx[16];
    __shared__ int   s_rad;
    __shared__ float s_red[4];

    int radius = radius_raw[row] + 1;          // [1,15]

    if (wid == 0) {
        if (lane == 0) s_rad = radius;
        // candidates: 2 per lane
        float v0 = g_cv[row * 64 + lane],      v1 = g_cv[row * 64 + 32 + lane];
        int   i0 = g_ci[row * 64 + lane],      i1 = g_ci[row * 64 + 32 + lane];
        #pragma unroll 1
        for (int t = 0; t < radius; t++) {
            float bv; int bi;
            if (v0 > v1 || (v0 == v1 && i0 < i1)) { bv = v0; bi = i0; } else { bv = v1; bi = i1; }
            warp_argmax(bv, bi);
            if (i0 == bi) v0 = -FLT_MAX;
            if (i1 == bi) v1 = -FLT_MAX;
            if (lane == 0) { s_idx[t] = bi; g_fidx[row * 16 + t] = bi; }
        }
    }
    __syncthreads();
    radius = s_rad;

    // quad = 0.5 * d^T W d over flipped positions (all 128 threads)
    const float* xr = x + (size_t)row * DD;
    float q = 0.f;
    int rr = radius * radius;
    for (int p = tid; p < rr; p += 128) {
        int a = p / radius, bb = p - a * radius;
        int ia = s_idx[a], ib = s_idx[bb];
        float da = 1.f - 2.f * xr[ia];
        float db = 1.f - 2.f * xr[ib];
        q += da * db * W[(size_t)ia * DD + ib];
    }
    #pragma unroll
    for (int o = 16; o > 0; o >>= 1) q += __shfl_xor_sync(0xffffffffu, q, o);
    if (lane == 0) s_red[wid] = q;
    __syncthreads();

    if (wid == 0) {
        float quad = 0.5f * (s_red[0] + s_red[1] + s_red[2] + s_red[3]);

        // lse_x from 4 chunk partials (each lane redundantly)
        float M = g_pm[row * 4];
        #pragma unroll
        for (int c = 1; c < 4; c++) M = fmaxf(M, g_pm[row * 4 + c]);
        float ss = 0.f;
        #pragma unroll
        for (int c = 0; c < 4; c++) ss += g_ps[row * 4 + c] * __expf(g_pm[row * 4 + c] - M);
        float lse_x = M + logf(ss);

        // lse_y correction: lanes t < radius recompute scx at flipped idx
        float corr = 0.f;
        if (lane < radius) {
            int j = s_idx[lane];
            float xj = xr[j];
            float gj = g_grad[(size_t)row * DD + j];
            float scxj = (0.5f - xj) * gj;
            corr = __expf(-scxj - M) - __expf(scxj - M);
        }
        #pragma unroll
        for (int o = 16; o > 0; o >>= 1) corr += __shfl_xor_sync(0xffffffffu, corr, o);
        float lse_y = M + logf(ss + corr);

        float la = fminf(quad + lse_x - lse_y, 0.f);
        int accept = (__expf(la) > u[row]) ? 1 : 0;
        if (lane == 0) g_cnt[row] = accept ? radius : 0;
    }
}

// ---------------------------------------------------------------------------
// Kernel 4c: apply flips. Grid (4, BD), 256 threads.
// ---------------------------------------------------------------------------
__global__ __launch_bounds__(256) void k_apply(
    const float* __restrict__ x, float* __restrict__ out)
{
    int chunk = blockIdx.x, row = blockIdx.y;
    int tid = threadIdx.x;
    __shared__ int s_f[16];
    __shared__ int s_c;

    if (tid == 0) s_c = g_cnt[row];
    if (tid < 16) s_f[tid] = g_fidx[row * 16 + tid];
    __syncthreads();
    int cnt = s_c;

    size_t goff = (size_t)row * DD + chunk * 1024 + tid * 4;
    float4 v = *(const float4*)&x[goff];
    float* pv = (float*)&v;
    int gbase = chunk * 1024 + tid * 4;
    for (int t = 0; t < cnt; t++) {
        int j = s_f[t];
        int rel = j - gbase;
        if (rel >= 0 && rel < 4) pv[rel] = 1.f - pv[rel];
    }
    *(float4*)&out[goff] = v;
}

// ---------------------------------------------------------------------------
extern "C" void kernel_launch(void* const* d_in, const int* in_sizes, int n_in,
                              void* d_out, int out_size) {
    const float* x          = (const float*)d_in[0];
    const float* W          = (const float*)d_in[1];
    const float* bias       = (const float*)d_in[2];
    const int*   radius_raw = (const int*)d_in[3];
    const float* gum        = (const float*)d_in[4];
    const float* u          = (const float*)d_in[5];
    float* out = (float*)d_out;

    cudaFuncSetAttribute(k_gemm, cudaFuncAttributeMaxDynamicSharedMemorySize, GSMEM);

    k_buildM<<<dim3(DD / 64, DD / 64), 256>>>(W);
    k_convX<<<(BD * DD) / 1024, 256>>>(x);
    k_gemm<<<dim3(DD / TN, BD / TM), 128, GSMEM>>>(bias);
    k_part<<<dim3(4, BD), 256>>>(x, gum);
    k_fin<<<BD, 128>>>(x, W, radius_raw, u);
    k_apply<<<dim3(4, BD), 256>>>(x, out);
}